// round 6
// baseline (speedup 1.0000x reference)
#include <cuda_runtime.h>
#include <cuda_fp16.h>
#include <math.h>

#define NB    64
#define NI    2048
#define KA    8
#define NO    32
#define OA    16
#define OUT   512

__device__ float g_preact[3][NB * OUT];   // per-iteration preact accumulators
// votes fp16 as uint4 (8 halves = atoms 8c..8c+7 of capsule j=lane)
// index: ((b*NI + i)*2 + c)*32 + lane    -> 128 MB
__device__ uint4 g_votes[(size_t)NB * NI * 2 * 32];

typedef unsigned long long u64;

// ---- f32x2 helpers ----
__device__ __forceinline__ u64 fma2(u64 a, u64 b, u64 c) {
    u64 d; asm("fma.rn.f32x2 %0, %1, %2, %3;" : "=l"(d) : "l"(a), "l"(b), "l"(c)); return d;
}
__device__ __forceinline__ u64 pack2(float lo, float hi) {
    u64 d; asm("mov.b64 %0, {%1, %2};" : "=l"(d) : "f"(lo), "f"(hi)); return d;
}
__device__ __forceinline__ void unpack2(u64 v, float& lo, float& hi) {
    asm("mov.b64 {%0, %1}, %2;" : "=f"(lo), "=f"(hi) : "l"(v));
}
__device__ __forceinline__ void cp16(void* smem_dst, const void* gsrc) {
    unsigned s = (unsigned)__cvta_generic_to_shared(smem_dst);
    asm volatile("cp.async.cg.shared.global [%0], [%1], 16;" :: "r"(s), "l"(gsrc));
}
__device__ __forceinline__ int swz(int b) { return b ^ ((b >> 3) & 0x70); }

__device__ __forceinline__ u64 h2f2(unsigned h) {       // half2 -> packed f32x2
    float2 f = __half22float2(*(__half2*)&h);
    return pack2(f.x, f.y);
}

// ---------------------------------------------------------------- zero
__global__ void k_zero() {
    int t = blockIdx.x * blockDim.x + threadIdx.x;
    if (t < 3 * NB * OUT) ((float*)g_preact)[t] = 0.0f;
}

// ---------------------------------------------------------------- gen + pass0
// grid = (NI/32, NB/32), block 512 (16 warps). lane = j; warp owns 2 b.
// W[i] staged in smem (cp.async dbl buffer). Stores fp16 votes (uint4,
// coalesced) and accumulates pass-0 preact (route = 1/33) into g_preact[0].
#define ITA 32
__global__ void __launch_bounds__(512, 1)
k_gen(const float* __restrict__ x, const float* __restrict__ W) {
    __shared__ char ws[2 * KA * OUT * 4];     // 32 KB dbl-buffered W tile

    const int tid  = threadIdx.x;
    const int w    = tid >> 5;
    const int lane = tid & 31;
    const int it0  = blockIdx.x * ITA;
    const int b0   = blockIdx.y * 32 + w * 2;

    {   // prefetch first tile (16 KB = 1024 float4, 2 per thread)
        const float4* g = (const float4*)(W + (size_t)it0 * KA * OUT);
#pragma unroll
        for (int r = 0; r < 2; r++) { int f4 = tid + 512 * r; cp16(ws + swz(f4 * 16), &g[f4]); }
        asm volatile("cp.async.commit_group;" ::: "memory");
    }

    u64 acc[2][8];
#pragma unroll
    for (int bq = 0; bq < 2; bq++)
#pragma unroll
        for (int p = 0; p < 8; p++) acc[bq][p] = 0ull;
    const u64 c33 = pack2(1.0f / 33.0f, 1.0f / 33.0f);

    for (int ii = 0; ii < ITA; ii++) {
        asm volatile("cp.async.wait_group 0;" ::: "memory");
        __syncthreads();

        if (ii + 1 < ITA) {
            const float4* g = (const float4*)(W + (size_t)(it0 + ii + 1) * KA * OUT);
            char* dst = ws + ((ii + 1) & 1) * (KA * OUT * 4);
#pragma unroll
            for (int r = 0; r < 2; r++) { int f4 = tid + 512 * r; cp16(dst + swz(f4 * 16), &g[f4]); }
            asm volatile("cp.async.commit_group;" ::: "memory");
        }

        const char* Wc = ws + (ii & 1) * (KA * OUT * 4);
        const int i = it0 + ii;

        float xk[2][KA];
#pragma unroll
        for (int bq = 0; bq < 2; bq++) {
            const float4* xp = (const float4*)&x[((size_t)(b0 + bq) * NI + i) * KA];
            float4 x0 = __ldg(xp), x1 = __ldg(xp + 1);
            xk[bq][0]=x0.x; xk[bq][1]=x0.y; xk[bq][2]=x0.z; xk[bq][3]=x0.w;
            xk[bq][4]=x1.x; xk[bq][5]=x1.y; xk[bq][6]=x1.z; xk[bq][7]=x1.w;
        }

        u64 v[2][8];
#pragma unroll
        for (int bq = 0; bq < 2; bq++)
#pragma unroll
            for (int p = 0; p < 8; p++) v[bq][p] = 0ull;

#pragma unroll
        for (int k = 0; k < KA; k++) {
            u64 xb0 = pack2(xk[0][k], xk[0][k]);
            u64 xb1 = pack2(xk[1][k], xk[1][k]);
#pragma unroll
            for (int q = 0; q < 4; q++) {
                ulonglong2 wv = *(const ulonglong2*)(Wc + swz(k * 2048 + lane * 64 + q * 16));
                v[0][2*q]   = fma2(xb0, wv.x, v[0][2*q]);
                v[0][2*q+1] = fma2(xb0, wv.y, v[0][2*q+1]);
                v[1][2*q]   = fma2(xb1, wv.x, v[1][2*q]);
                v[1][2*q+1] = fma2(xb1, wv.y, v[1][2*q+1]);
            }
        }

#pragma unroll
        for (int bq = 0; bq < 2; bq++) {
            unsigned h[8];
#pragma unroll
            for (int p = 0; p < 8; p++) {
                acc[bq][p] = fma2(c33, v[bq][p], acc[bq][p]);
                float f0, f1; unpack2(v[bq][p], f0, f1);
                __half2 hh = __floats2half2_rn(f0, f1);
                h[p] = *(unsigned*)&hh;
            }
            uint4* dst = &g_votes[(((size_t)(b0 + bq) * NI + i) * 2) * 32 + lane];
            dst[0]  = make_uint4(h[0], h[1], h[2], h[3]);
            dst[32] = make_uint4(h[4], h[5], h[6], h[7]);
        }
    }

#pragma unroll
    for (int bq = 0; bq < 2; bq++) {
        float* dst = &g_preact[0][(size_t)(b0 + bq) * OUT + lane * OA];
#pragma unroll
        for (int p = 0; p < 8; p++) {
            float a0, a1; unpack2(acc[bq][p], a0, a1);
            atomicAdd(dst + 2*p, a0);
            atomicAdd(dst + 2*p + 1, a1);
        }
    }
}

// ---------------------------------------------------------------- route pass R
// grid = (16, NB), block 256 (8 warps). warp = 16-i chunk of batch b; lane = j.
// Prologue recomputes S = sum_{t<R} squash(preact[t]+bias) in-thread.
// Main loop: software-pipelined groups of 4 i (8 LDG.128 always in flight),
// 4 softmaxes interleaved (parallel shfl rounds), acc -> g_preact[R].
#define IW 16
#define GRP 4
template<int R>
__global__ void __launch_bounds__(256)
k_pass(const float* __restrict__ bias) {
    const int tid  = threadIdx.x;
    const int w    = tid >> 5;
    const int lane = tid & 31;
    const int b    = blockIdx.y;
    const int i0   = (blockIdx.x * 8 + w) * IW;

    // S for (b, j=lane, 16 atoms) computed in-thread (idempotent across blocks).
    float sf[OA];
#pragma unroll
    for (int a = 0; a < OA; a++) sf[a] = 0.0f;
#pragma unroll
    for (int t = 0; t < R; t++) {
        const float4* pp = (const float4*)&g_preact[t][(size_t)b * OUT + lane * OA];
        const float4* bb = (const float4*)&bias[lane * OA];
        float p[OA]; float sq = 0.0f;
#pragma unroll
        for (int q = 0; q < 4; q++) {
            float4 pv = __ldg(pp + q), bv = __ldg(bb + q);
            p[4*q]=pv.x+bv.x; p[4*q+1]=pv.y+bv.y; p[4*q+2]=pv.z+bv.z; p[4*q+3]=pv.w+bv.w;
        }
#pragma unroll
        for (int a = 0; a < OA; a++) sq = fmaf(p[a], p[a], sq);
        float scale = sqrtf(sq) / (1.0f + sq);
#pragma unroll
        for (int a = 0; a < OA; a++) sf[a] = fmaf(p[a], scale, sf[a]);
    }
    u64 s[8];
#pragma unroll
    for (int p = 0; p < 8; p++) s[p] = pack2(sf[2*p], sf[2*p+1]);

    u64 acc[8];
#pragma unroll
    for (int p = 0; p < 8; p++) acc[p] = 0ull;

    const uint4* src = &g_votes[(((size_t)b * NI + i0) * 2) * 32 + lane];

    // Double-buffered groups of GRP=4 i's; 2 LDG.128 per i.
    uint4 buf[2][2 * GRP];
#pragma unroll
    for (int mm = 0; mm < GRP; mm++) {
        buf[0][2*mm]   = __ldg(src + (size_t)mm * 64);
        buf[0][2*mm+1] = __ldg(src + (size_t)mm * 64 + 32);
    }

#pragma unroll
    for (int g = 0; g < IW / GRP; g++) {
        const int cur = g & 1;
        if (g + 1 < IW / GRP) {          // prefetch next group -> 8 loads in flight
            const uint4* ns = src + (size_t)(g + 1) * GRP * 64;
#pragma unroll
            for (int mm = 0; mm < GRP; mm++) {
                buf[cur ^ 1][2*mm]   = __ldg(ns + (size_t)mm * 64);
                buf[cur ^ 1][2*mm+1] = __ldg(ns + (size_t)mm * 64 + 32);
            }
        }

        // convert + logits for 4 independent i's
        u64 v[GRP][8];
        float e[GRP], tot[GRP];
#pragma unroll
        for (int mm = 0; mm < GRP; mm++) {
            uint4 u0 = buf[cur][2*mm], u1 = buf[cur][2*mm+1];
            v[mm][0]=h2f2(u0.x); v[mm][1]=h2f2(u0.y); v[mm][2]=h2f2(u0.z); v[mm][3]=h2f2(u0.w);
            v[mm][4]=h2f2(u1.x); v[mm][5]=h2f2(u1.y); v[mm][6]=h2f2(u1.z); v[mm][7]=h2f2(u1.w);
            u64 l2 = 0ull;
#pragma unroll
            for (int p = 0; p < 8; p++) l2 = fma2(v[mm][p], s[p], l2);
            float a0, a1; unpack2(l2, a0, a1);
            e[mm] = __expf(a0 + a1);
            tot[mm] = e[mm];
        }
        // 4 parallel shfl reductions (independent chains)
#pragma unroll
        for (int d = 16; d > 0; d >>= 1) {
#pragma unroll
            for (int mm = 0; mm < GRP; mm++)
                tot[mm] += __shfl_xor_sync(0xFFFFFFFFu, tot[mm], d);
        }
#pragma unroll
        for (int mm = 0; mm < GRP; mm++) {
            float r = __fdividef(e[mm], 1.0f + tot[mm]);   // leaky softmax
            u64 r2 = pack2(r, r);
#pragma unroll
            for (int p = 0; p < 8; p++) acc[p] = fma2(r2, v[mm][p], acc[p]);
        }
    }

    float* dst = &g_preact[R][(size_t)b * OUT + lane * OA];
#pragma unroll
    for (int p = 0; p < 8; p++) {
        float a0, a1; unpack2(acc[p], a0, a1);
        atomicAdd(dst + 2*p, a0);
        atomicAdd(dst + 2*p + 1, a1);
    }
}

// ---------------------------------------------------------------- final squash
__global__ void k_final(const float* __restrict__ bias, float* __restrict__ out) {
    const int b = blockIdx.x;
    const int t = threadIdx.x;

    float p = g_preact[2][b * OUT + t] + bias[t];
    float sq = p * p;
#pragma unroll
    for (int d = 1; d < OA; d <<= 1)
        sq += __shfl_xor_sync(0xFFFFFFFFu, sq, d);
    float nrm = sqrtf(sq);
    out[b * OUT + t] = p * (nrm / (1.0f + sq));
}

// ---------------------------------------------------------------- launch
extern "C" void kernel_launch(void* const* d_in, const int* in_sizes, int n_in,
                              void* d_out, int out_size) {
    const float* x    = (const float*)d_in[0];   // [64, 2048, 8]
    const float* W    = (const float*)d_in[1];   // [2048, 8, 512]
    const float* bias = (const float*)d_in[2];   // [32, 16]
    float* out = (float*)d_out;                  // [64, 32, 16]

    k_zero<<<192, 512>>>();
    k_gen<<<dim3(NI / ITA, NB / 32), 512>>>(x, W);   // votes + pass 0
    k_pass<1><<<dim3(16, NB), 256>>>(bias);
    k_pass<2><<<dim3(16, NB), 256>>>(bias);
    k_final<<<NB, 512>>>(bias, out);
}

// round 8
// speedup vs baseline: 1.1953x; 1.1953x over previous
#include <cuda_runtime.h>
#include <cuda_fp16.h>
#include <math.h>

#define NB    64
#define NI    2048
#define KA    8
#define NO    32
#define OA    16
#define OUT   512

__device__ float g_S[NB * OUT];        // cumulative sum of activations
__device__ float g_preact[NB * OUT];
// votes fp16, SoA-chunked: uint2 (4 halves = atoms 4c..4c+3 of capsule j=lane)
// index: ((b*NI + i)*4 + c)*32 + lane          -> 128 MB
__device__ uint2 g_votes[(size_t)NB * NI * 4 * 32];

typedef unsigned long long u64;

// ---- f32x2 helpers ----
__device__ __forceinline__ u64 fma2(u64 a, u64 b, u64 c) {
    u64 d; asm("fma.rn.f32x2 %0, %1, %2, %3;" : "=l"(d) : "l"(a), "l"(b), "l"(c)); return d;
}
__device__ __forceinline__ u64 pack2(float lo, float hi) {
    u64 d; asm("mov.b64 %0, {%1, %2};" : "=l"(d) : "f"(lo), "f"(hi)); return d;
}
__device__ __forceinline__ void unpack2(u64 v, float& lo, float& hi) {
    asm("mov.b64 {%0, %1}, %2;" : "=f"(lo), "=f"(hi) : "l"(v));
}
__device__ __forceinline__ void cp16(void* smem_dst, const void* gsrc) {
    unsigned s = (unsigned)__cvta_generic_to_shared(smem_dst);
    asm volatile("cp.async.cg.shared.global [%0], [%1], 16;" :: "r"(s), "l"(gsrc));
}
__device__ __forceinline__ int swz(int b) { return b ^ ((b >> 3) & 0x70); }

// ---------------------------------------------------------------- zero
__global__ void k_zero() {
    int t = blockIdx.x * blockDim.x + threadIdx.x;
    if (t < NB * OUT) { g_S[t] = 0.0f; g_preact[t] = 0.0f; }
}

// ---------------------------------------------------------------- gen + pass0
// grid = (NI/32, NB/32), block 512 (16 warps). lane = j; warp owns 2 b.
// W[i] staged in smem (cp.async dbl buffer). Stores fp16 votes (uint2,
// coalesced) and accumulates pass-0 preact (route = 1/33).
#define ITA 32
__global__ void __launch_bounds__(512, 1)
k_gen(const float* __restrict__ x, const float* __restrict__ W) {
    __shared__ char ws[2 * KA * OUT * 4];     // 32 KB dbl-buffered W tile

    const int tid  = threadIdx.x;
    const int w    = tid >> 5;
    const int lane = tid & 31;
    const int it0  = blockIdx.x * ITA;
    const int b0   = blockIdx.y * 32 + w * 2;

    {   // prefetch first tile (16 KB = 1024 float4, 2 per thread)
        const float4* g = (const float4*)(W + (size_t)it0 * KA * OUT);
#pragma unroll
        for (int r = 0; r < 2; r++) { int f4 = tid + 512 * r; cp16(ws + swz(f4 * 16), &g[f4]); }
        asm volatile("cp.async.commit_group;" ::: "memory");
    }

    u64 acc[2][8];
#pragma unroll
    for (int bq = 0; bq < 2; bq++)
#pragma unroll
        for (int p = 0; p < 8; p++) acc[bq][p] = 0ull;
    const u64 c33 = pack2(1.0f / 33.0f, 1.0f / 33.0f);

    for (int ii = 0; ii < ITA; ii++) {
        asm volatile("cp.async.wait_group 0;" ::: "memory");
        __syncthreads();

        if (ii + 1 < ITA) {
            const float4* g = (const float4*)(W + (size_t)(it0 + ii + 1) * KA * OUT);
            char* dst = ws + ((ii + 1) & 1) * (KA * OUT * 4);
#pragma unroll
            for (int r = 0; r < 2; r++) { int f4 = tid + 512 * r; cp16(dst + swz(f4 * 16), &g[f4]); }
            asm volatile("cp.async.commit_group;" ::: "memory");
        }

        const char* Wc = ws + (ii & 1) * (KA * OUT * 4);
        const int i = it0 + ii;

        float xk[2][KA];
#pragma unroll
        for (int bq = 0; bq < 2; bq++) {
            const float4* xp = (const float4*)&x[((size_t)(b0 + bq) * NI + i) * KA];
            float4 x0 = __ldg(xp), x1 = __ldg(xp + 1);
            xk[bq][0]=x0.x; xk[bq][1]=x0.y; xk[bq][2]=x0.z; xk[bq][3]=x0.w;
            xk[bq][4]=x1.x; xk[bq][5]=x1.y; xk[bq][6]=x1.z; xk[bq][7]=x1.w;
        }

        u64 v[2][8];
#pragma unroll
        for (int bq = 0; bq < 2; bq++)
#pragma unroll
            for (int p = 0; p < 8; p++) v[bq][p] = 0ull;

#pragma unroll
        for (int k = 0; k < KA; k++) {
            u64 xb0 = pack2(xk[0][k], xk[0][k]);
            u64 xb1 = pack2(xk[1][k], xk[1][k]);
#pragma unroll
            for (int q = 0; q < 4; q++) {
                ulonglong2 wv = *(const ulonglong2*)(Wc + swz(k * 2048 + lane * 64 + q * 16));
                v[0][2*q]   = fma2(xb0, wv.x, v[0][2*q]);
                v[0][2*q+1] = fma2(xb0, wv.y, v[0][2*q+1]);
                v[1][2*q]   = fma2(xb1, wv.x, v[1][2*q]);
                v[1][2*q+1] = fma2(xb1, wv.y, v[1][2*q+1]);
            }
        }

#pragma unroll
        for (int bq = 0; bq < 2; bq++) {
            unsigned h[8];
#pragma unroll
            for (int p = 0; p < 8; p++) {
                acc[bq][p] = fma2(c33, v[bq][p], acc[bq][p]);
                float f0, f1; unpack2(v[bq][p], f0, f1);
                __half2 hh = __floats2half2_rn(f0, f1);
                h[p] = *(unsigned*)&hh;
            }
            uint2* dst = &g_votes[(((size_t)(b0 + bq) * NI + i) * 4) * 32 + lane];
#pragma unroll
            for (int c = 0; c < 4; c++)
                dst[c * 32] = make_uint2(h[2*c], h[2*c+1]);
        }
    }

#pragma unroll
    for (int bq = 0; bq < 2; bq++) {
        float* dst = &g_preact[(size_t)(b0 + bq) * OUT + lane * OA];
#pragma unroll
        for (int p = 0; p < 8; p++) {
            float a0, a1; unpack2(acc[bq][p], a0, a1);
            atomicAdd(dst + 2*p, a0);
            atomicAdd(dst + 2*p + 1, a1);
        }
    }
}

// ---------------------------------------------------------------- route pass
// grid = (8, 64): warp = (b = by, i-chunk of 32 i), lane = j.  Exact R4
// structure (unroll-4, 4x LDG.64 per i).  REV=1 walks chunks high-i-first so
// this pass's reads hit the votes tail left resident in L2 by the previous
// kernel; it leaves the opposite tail for the next pass (which uses REV=0).
#define IW 32
template<int REV>
__global__ void __launch_bounds__(256)
k_pass() {
    const int tid  = threadIdx.x;
    const int w    = tid >> 5;
    const int lane = tid & 31;
    const int b    = blockIdx.y;
    int chunk = blockIdx.x * 8 + w;               // [0, 64)
    if (REV) chunk = 63 - chunk;
    const int i0 = chunk * IW;

    // S[b, lane*16 .. +16) in 8 u64 regs
    u64 s[8];
    {
        const ulonglong2* sp = (const ulonglong2*)&g_S[(size_t)b * OUT + lane * OA];
#pragma unroll
        for (int q = 0; q < 4; q++) { ulonglong2 t = __ldg(sp + q); s[2*q] = t.x; s[2*q+1] = t.y; }
    }

    u64 acc[8];
#pragma unroll
    for (int p = 0; p < 8; p++) acc[p] = 0ull;

    const uint2* src = &g_votes[(((size_t)b * NI + i0) * 4) * 32 + lane];

#pragma unroll 4
    for (int m = 0; m < IW; m++) {
        uint2 u[4];
#pragma unroll
        for (int c = 0; c < 4; c++) u[c] = __ldg(src + (size_t)m * 128 + c * 32);

        u64 v[8];
#pragma unroll
        for (int c = 0; c < 4; c++) {
            float2 f0 = __half22float2(*(__half2*)&u[c].x);
            float2 f1 = __half22float2(*(__half2*)&u[c].y);
            v[2*c]   = pack2(f0.x, f0.y);
            v[2*c+1] = pack2(f1.x, f1.y);
        }

        u64 l2 = 0ull;
#pragma unroll
        for (int p = 0; p < 8; p++) l2 = fma2(v[p], s[p], l2);
        float a0, a1; unpack2(l2, a0, a1);
        float e = __expf(a0 + a1);

        float tot = e;
#pragma unroll
        for (int d = 16; d > 0; d >>= 1)
            tot += __shfl_xor_sync(0xFFFFFFFFu, tot, d);
        float r = __fdividef(e, 1.0f + tot);       // leaky softmax (leak logit 0)

        u64 r2 = pack2(r, r);
#pragma unroll
        for (int p = 0; p < 8; p++) acc[p] = fma2(r2, v[p], acc[p]);
    }

    float* dst = &g_preact[(size_t)b * OUT + lane * OA];
#pragma unroll
    for (int p = 0; p < 8; p++) {
        float a0, a1; unpack2(acc[p], a0, a1);
        atomicAdd(dst + 2*p, a0);
        atomicAdd(dst + 2*p + 1, a1);
    }
}

// ---------------------------------------------------------------- squash
__global__ void k_squash(const float* __restrict__ bias, float* __restrict__ out) {
    const int b = blockIdx.x;
    const int t = threadIdx.x;

    float p = g_preact[b * OUT + t] + bias[t];
    float sq = p * p;
#pragma unroll
    for (int d = 1; d < OA; d <<= 1)
        sq += __shfl_xor_sync(0xFFFFFFFFu, sq, d);
    float nrm = sqrtf(sq);
    float scale = nrm / (1.0f + sq);
    float a = p * scale;

    out[b * OUT + t] = a;
    g_S[b * OUT + t] += a;
    g_preact[b * OUT + t] = 0.0f;
}

// ---------------------------------------------------------------- launch
extern "C" void kernel_launch(void* const* d_in, const int* in_sizes, int n_in,
                              void* d_out, int out_size) {
    const float* x    = (const float*)d_in[0];   // [64, 2048, 8]
    const float* W    = (const float*)d_in[1];   // [2048, 8, 512]
    const float* bias = (const float*)d_in[2];   // [32, 16]
    float* out = (float*)d_out;                  // [64, 32, 16]

    k_zero<<<64, 512>>>();
    k_gen<<<dim3(NI / ITA, NB / 32), 512>>>(x, W);   // votes + pass 0
    k_squash<<<NB, 512>>>(bias, out);
    k_pass<1><<<dim3(8, NB), 256>>>();               // pass 1: reverse (hit L2 tail)
    k_squash<<<NB, 512>>>(bias, out);
    k_pass<0><<<dim3(8, NB), 256>>>();               // pass 2: forward
    k_squash<<<NB, 512>>>(bias, out);
}